// round 11
// baseline (speedup 1.0000x reference)
#include <cuda_runtime.h>
#include <cuda_fp16.h>
#include <math.h>
#include <stdint.h>

// Problem constants: B=2, S=1024 -> T=2048 tokens; D=768; E=8 experts; DFF=3072; top-2.
#define T    2048
#define D    768
#define E    8
#define DFF  3072

// GEMM tiling: 128x192 CTA tile, 384 threads (12 warps, 3/SMSP), warps 2x6,
// 64x32 warp tiles, BK=64 (4 sub-k16), fp16 mma.sync + ldmatrix, 3-stage cp.async.
#define BM 128
#define BN 192
#define BK 64
#define SA 72                       // smem row stride (halves): 64 + 8 pad
#define STAGES 3
#define STG_ROWS (BM + BN)          // 320 rows (A then B) per stage
#define STG_BYTES (STG_ROWS * SA * 2)   // 46080 B per stage
#define SMEM_TOT (STAGES * STG_BYTES)   // 138240 B
#define NCHUNK (STG_ROWS * (BK / 8))    // 2560 16B chunks per stage
#define SPLITK 4
#define NTHREADS 384

// ---------------------------------------------------------------------------
// Device scratch
// ---------------------------------------------------------------------------
__device__ int    g_cnt[E];
__device__ int    g_tok[E * T];
__device__ int    g_rowof[T * 2];
__device__ float  g_w[T * 2];
__device__ __half g_xh[T * D];                    // x in fp16
__device__ __half g_W1h[(size_t)E * DFF * D];     // W1 in fp16
__device__ __half g_W2h[(size_t)E * D * DFF];     // W2 in fp16
__device__ __half g_Hh[(size_t)E * T * DFF];      // hidden acts, fp16
__device__ float  g_Y[SPLITK][E * T * D];         // split-K partial outputs

__global__ void reset_kernel() {
    if (threadIdx.x < E) g_cnt[threadIdx.x] = 0;
}

// ---------------------------------------------------------------------------
// helpers
// ---------------------------------------------------------------------------
__device__ __forceinline__ uint4 pack8(float4 a, float4 b) {
    __half2 h0 = __floats2half2_rn(a.x, a.y);
    __half2 h1 = __floats2half2_rn(a.z, a.w);
    __half2 h2 = __floats2half2_rn(b.x, b.y);
    __half2 h3 = __floats2half2_rn(b.z, b.w);
    uint4 u;
    u.x = *reinterpret_cast<uint32_t*>(&h0);
    u.y = *reinterpret_cast<uint32_t*>(&h1);
    u.z = *reinterpret_cast<uint32_t*>(&h2);
    u.w = *reinterpret_cast<uint32_t*>(&h3);
    return u;
}
__device__ __forceinline__ uint32_t smem_u32(const void* p) {
    return (uint32_t)__cvta_generic_to_shared(p);
}
__device__ __forceinline__ void cp16(uint32_t dst, const void* src) {
    asm volatile("cp.async.cg.shared.global [%0], [%1], 16;"
                 :: "r"(dst), "l"(src) : "memory");
}
__device__ __forceinline__ void cp_commit() {
    asm volatile("cp.async.commit_group;" ::: "memory");
}
template <int N>
__device__ __forceinline__ void cp_wait() {
    asm volatile("cp.async.wait_group %0;" :: "n"(N) : "memory");
}
__device__ __forceinline__ void ldsm4(uint32_t& r0, uint32_t& r1, uint32_t& r2, uint32_t& r3,
                                      uint32_t addr) {
    asm volatile("ldmatrix.sync.aligned.m8n8.x4.shared.b16 {%0,%1,%2,%3}, [%4];"
                 : "=r"(r0), "=r"(r1), "=r"(r2), "=r"(r3) : "r"(addr));
}
__device__ __forceinline__ void mma_f16(float& c0, float& c1, float& c2, float& c3,
                                        uint32_t a0, uint32_t a1, uint32_t a2, uint32_t a3,
                                        uint32_t b0, uint32_t b1) {
    asm volatile(
        "mma.sync.aligned.m16n8k16.row.col.f32.f16.f16.f32 "
        "{%0,%1,%2,%3}, {%4,%5,%6,%7}, {%8,%9}, {%0,%1,%2,%3};"
        : "+f"(c0), "+f"(c1), "+f"(c2), "+f"(c3)
        : "r"(a0), "r"(a1), "r"(a2), "r"(a3), "r"(b0), "r"(b1));
}

// ---------------------------------------------------------------------------
// Fused fp32->fp16 convert (x, W1, W2) + router. Disjoint block ranges; no
// data dependency (router reads fp32 x). Router: one warp per token, noisy
// top-2 gating + atomic per-expert compaction (position-invariant values ->
// deterministic output).
// ---------------------------------------------------------------------------
__device__ void router_body(int warp, int lane,
                            const float* __restrict__ x,
                            const float* __restrict__ noise,
                            const float* __restrict__ Wg,
                            const float* __restrict__ bg,
                            const float* __restrict__ Wn,
                            const float* __restrict__ bn)
{
    const float* xr = x + (size_t)warp * D;
    float xv[D / 32];
    #pragma unroll
    for (int i = 0; i < D / 32; i++) xv[i] = xr[lane + 32 * i];

    float nz[E];
    #pragma unroll
    for (int e = 0; e < E; e++) {
        const float* g  = Wg + e * D;
        const float* nw = Wn + e * D;
        float s1 = 0.f, s2 = 0.f;
        #pragma unroll
        for (int i = 0; i < D / 32; i++) {
            const float xi = xv[i];
            s1 = fmaf(xi, g[lane + 32 * i], s1);
            s2 = fmaf(xi, nw[lane + 32 * i], s2);
        }
        #pragma unroll
        for (int off = 16; off; off >>= 1) {
            s1 += __shfl_xor_sync(0xffffffffu, s1, off);
            s2 += __shfl_xor_sync(0xffffffffu, s2, off);
        }
        const float logit = s1 + bg[e];
        const float nlog  = s2 + bn[e];
        const float sp = fmaxf(nlog, 0.f) + log1pf(expf(-fabsf(nlog)));
        nz[e] = logit + noise[warp * E + e] * sp;
    }

    if (lane == 0) {
        int i0 = 0; float v0 = nz[0];
        #pragma unroll
        for (int e = 1; e < E; e++) if (nz[e] > v0) { v0 = nz[e]; i0 = e; }
        int i1 = -1; float v1 = -3.0e38f;
        #pragma unroll
        for (int e = 0; e < E; e++) if (e != i0 && nz[e] > v1) { v1 = nz[e]; i1 = e; }

        const float ex = expf(v1 - v0);
        const float inv = 1.f / (1.f + ex);

        const int p0 = atomicAdd(&g_cnt[i0], 1);
        const int p1 = atomicAdd(&g_cnt[i1], 1);
        const int r0 = i0 * T + p0;
        const int r1 = i1 * T + p1;
        g_tok[r0] = warp;
        g_tok[r1] = warp;
        g_rowof[2 * warp]     = r0;
        g_rowof[2 * warp + 1] = r1;
        g_w[2 * warp]     = inv;
        g_w[2 * warp + 1] = ex * inv;
    }
}

__global__ void cvt_router_kernel(const float* __restrict__ x,
                                  const float* __restrict__ W1,
                                  const float* __restrict__ W2,
                                  const float* __restrict__ noise,
                                  const float* __restrict__ Wg,
                                  const float* __restrict__ bg,
                                  const float* __restrict__ Wn,
                                  const float* __restrict__ bn,
                                  __half* __restrict__ xh,
                                  __half* __restrict__ w1h,
                                  __half* __restrict__ w2h,
                                  int nx8, int nw8, int cvtBlocks)
{
    if ((int)blockIdx.x < cvtBlocks) {
        const int i = blockIdx.x * blockDim.x + threadIdx.x;
        const float* src; __half* dst; int j;
        if (i < nx8)                 { src = x;  dst = xh;  j = i; }
        else if (i < nx8 + nw8)      { src = W1; dst = w1h; j = i - nx8; }
        else if (i < nx8 + 2 * nw8)  { src = W2; dst = w2h; j = i - nx8 - nw8; }
        else return;
        const float4 a = reinterpret_cast<const float4*>(src)[2 * j];
        const float4 b = reinterpret_cast<const float4*>(src)[2 * j + 1];
        reinterpret_cast<uint4*>(dst)[j] = pack8(a, b);
    } else {
        const int warp = ((blockIdx.x - cvtBlocks) * blockDim.x + threadIdx.x) >> 5;
        const int lane = threadIdx.x & 31;
        if (warp < T) router_body(warp, lane, x, noise, Wg, bg, Wn, bn);
    }
}

// ---------------------------------------------------------------------------
// Fragment ops: warp tile 64x32. A: 4 ldsm.x4, B: 2 ldsm.x4 -> 16 MMAs.
// ---------------------------------------------------------------------------
__device__ __forceinline__ void load_frags(uint32_t (&af)[4][4], uint32_t (&bf)[4][2],
                                           const uint32_t (&aAddr)[4],
                                           const uint32_t (&bAddr)[2], uint32_t off)
{
    #pragma unroll
    for (int mi = 0; mi < 4; mi++)
        ldsm4(af[mi][0], af[mi][1], af[mi][2], af[mi][3], aAddr[mi] + off);
    #pragma unroll
    for (int p = 0; p < 2; p++) {
        uint32_t r0, r1, r2, r3;
        ldsm4(r0, r1, r2, r3, bAddr[p] + off);
        bf[2 * p][0] = r0;     bf[2 * p][1] = r1;
        bf[2 * p + 1][0] = r2; bf[2 * p + 1][1] = r3;
    }
}

__device__ __forceinline__ void mma_tile(float (&acc)[4][4][4],
                                         const uint32_t (&af)[4][4],
                                         const uint32_t (&bf)[4][2])
{
    #pragma unroll
    for (int mi = 0; mi < 4; mi++)
        #pragma unroll
        for (int ni = 0; ni < 4; ni++)
            mma_f16(acc[mi][ni][0], acc[mi][ni][1], acc[mi][ni][2], acc[mi][ni][3],
                    af[mi][0], af[mi][1], af[mi][2], af[mi][3],
                    bf[ni][0], bf[ni][1]);
}

// ---------------------------------------------------------------------------
// Grouped fp16 tensor-core GEMM. 128x192 tile, 384 threads, 64x32 warp tiles,
// BK=64 (4 sub-k16 per sync), 3-stage cp.async pipeline, pipelined fragments.
//   MODE 0: H = relu(gather(xh) @ W1h[e]^T + b1);   K=768,  N=3072, out fp16
//   MODE 1: Y = Hh @ W2h[e]^T (+b2 on split 0);     K=768/split x4, N=768, fp32
// ---------------------------------------------------------------------------
template <int MODE>
__global__ __launch_bounds__(NTHREADS, 1)
void gemm_f16_kernel(const __half* __restrict__ Wh,
                     const float* __restrict__ bias)
{
    constexpr int KROW = (MODE == 0) ? D : DFF;      // row stride of A and W
    constexpr int NTOT = (MODE == 0) ? DFF : D;
    constexpr int KLEN = (MODE == 0) ? D : (DFF / SPLITK);
    constexpr int NKT  = KLEN / BK;

    extern __shared__ __half sm[];

    int e, sK;
    if (MODE == 0) { e = blockIdx.z; sK = 0; }
    else           { e = blockIdx.z & (E - 1); sK = blockIdx.z >> 3; }
    const int ks0 = (MODE == 1) ? sK * KLEN : 0;

    const int cnt = g_cnt[e];
    const int m0  = blockIdx.y * BM;
    if (m0 >= cnt) return;
    const int n0  = blockIdx.x * BN;

    const int tid  = threadIdx.x;
    const int lane = tid & 31;
    const int warp = tid >> 5;         // 0..11
    const int wm   = warp / 6;         // 0..1  (64-row slices)
    const int wn   = warp % 6;         // 0..5  (32-col slices)
    const int g    = lane >> 2;
    const int q    = lane & 3;

    // ---- staging: 320 rows x 64 halves = 2560 16B-chunks; 7 per thread
    // (7th only for tid<256). chunk c = tid + 384k -> row c>>3, col (c&7)*8.
    const uint32_t smb = smem_u32(sm);
    const __half* srcP[7];
    uint32_t      stA[7];
    #pragma unroll
    for (int k = 0; k < 7; k++) {
        const int c  = tid + NTHREADS * k;
        const int rc = c >> 3;
        const int c8 = (c & 7) * 8;
        stA[k] = smb + (uint32_t)(rc * SA + c8) * 2;
        if (c < NCHUNK) {
            if (rc < BM) {
                const int am = m0 + rc;
                if (MODE == 0) {
                    const int tok = (am < cnt) ? g_tok[e * T + am] : 0;
                    srcP[k] = g_xh + (size_t)tok * KROW + c8;
                } else {
                    const int r = (am < cnt) ? am : 0;
                    srcP[k] = g_Hh + ((size_t)e * T + r) * KROW + ks0 + c8;
                }
            } else {
                srcP[k] = Wh + ((size_t)e * NTOT + n0 + (rc - BM)) * KROW + ks0 + c8;
            }
        } else {
            srcP[k] = Wh;   // never copied
        }
    }
    const bool has7 = (tid + NTHREADS * 6) < NCHUNK;

    // ---- ldmatrix lane base addresses (stage 0, sub-k 0) ----
    uint32_t aAddr[4], bAddr[2];
    {
        const int rin = lane & 15;
        const int ch  = lane >> 4;
        #pragma unroll
        for (int mi = 0; mi < 4; mi++)
            aAddr[mi] = smb + (uint32_t)((wm * 64 + mi * 16 + rin) * SA + ch * 8) * 2;
    }
    {
        const int rin = ((lane >> 4) << 3) + (lane & 7);
        const int ch  = (lane >> 3) & 1;
        #pragma unroll
        for (int p = 0; p < 2; p++)
            bAddr[p] = smb + (uint32_t)((BM + wn * 32 + p * 16 + rin) * SA + ch * 8) * 2;
    }

    float acc[4][4][4];
    #pragma unroll
    for (int mi = 0; mi < 4; mi++)
        #pragma unroll
        for (int ni = 0; ni < 4; ni++)
            #pragma unroll
            for (int r = 0; r < 4; r++) acc[mi][ni][r] = 0.f;

    // stage-fill helper (7 cp16 per thread, last predicated)
    auto FILL = [&](int stage, int kt) {
        const uint32_t so = (uint32_t)(stage * STG_BYTES);
        const int ko = kt * BK;
        #pragma unroll
        for (int k = 0; k < 6; k++)
            cp16(stA[k] + so, srcP[k] + ko);
        if (has7) cp16(stA[6] + so, srcP[6] + ko);
    };

    // prologue: fill stages 0..1
    #pragma unroll
    for (int s = 0; s < STAGES - 1; s++) { FILL(s, s); cp_commit(); }
    cp_wait<1>();                      // stage 0 complete
    __syncthreads();

    uint32_t af0[4][4], bf0[4][2], af1[4][4], bf1[4][2];
    load_frags(af0, bf0, aAddr, bAddr, 0);   // (kt=0, sub0)

    int cur = 0;
    for (int kt = 0; kt < NKT; kt++) {
        const uint32_t soff = (uint32_t)(cur * STG_BYTES);

        // sub1 frags, then next-stage cp.async, all under MMA(sub0)
        load_frags(af1, bf1, aAddr, bAddr, soff + 32);
        if (kt + STAGES - 1 < NKT) {
            int tgt = cur + 2; if (tgt >= STAGES) tgt -= STAGES;
            FILL(tgt, kt + STAGES - 1);
        }
        cp_commit();
        mma_tile(acc, af0, bf0);                       // sub0

        load_frags(af0, bf0, aAddr, bAddr, soff + 64); // sub2 frags
        mma_tile(acc, af1, bf1);                       // sub1

        load_frags(af1, bf1, aAddr, bAddr, soff + 96); // sub3 frags
        mma_tile(acc, af0, bf0);                       // sub2

        cp_wait<1>();                   // stage kt+1 complete
        __syncthreads();                // barrier drains under sub2's MMAs

        int nxt = cur + 1; if (nxt >= STAGES) nxt = 0;
        if (kt + 1 < NKT)               // (kt+1, sub0) frags under MMA(sub3)
            load_frags(af0, bf0, aAddr, bAddr, (uint32_t)(nxt * STG_BYTES));
        mma_tile(acc, af1, bf1);                       // sub3

        cur = nxt;
    }

    // ---- epilogue ----
    const float* be = bias + (size_t)e * NTOT;
    if (MODE == 0) {
        __half* Cb = g_Hh + (size_t)e * T * NTOT;
        #pragma unroll
        for (int mi = 0; mi < 4; mi++) {
            #pragma unroll
            for (int hh = 0; hh < 2; hh++) {
                const int m = m0 + wm * 64 + mi * 16 + g + hh * 8;
                if (m < cnt) {
                    __half* cr = Cb + (size_t)m * NTOT;
                    #pragma unroll
                    for (int ni = 0; ni < 4; ni++) {
                        const int c = n0 + wn * 32 + ni * 8 + 2 * q;
                        float v0 = acc[mi][ni][2 * hh]     + be[c];
                        float v1 = acc[mi][ni][2 * hh + 1] + be[c + 1];
                        v0 = fmaxf(v0, 0.f); v1 = fmaxf(v1, 0.f);
                        *reinterpret_cast<__half2*>(cr + c) = __floats2half2_rn(v0, v1);
                    }
                }
            }
        }
    } else {
        float* Cb = g_Y[sK] + (size_t)e * T * NTOT;
        #pragma unroll
        for (int mi = 0; mi < 4; mi++) {
            #pragma unroll
            for (int hh = 0; hh < 2; hh++) {
                const int m = m0 + wm * 64 + mi * 16 + g + hh * 8;
                if (m < cnt) {
                    float* cr = Cb + (size_t)m * NTOT;
                    #pragma unroll
                    for (int ni = 0; ni < 4; ni++) {
                        const int c = n0 + wn * 32 + ni * 8 + 2 * q;
                        float v0 = acc[mi][ni][2 * hh];
                        float v1 = acc[mi][ni][2 * hh + 1];
                        if (sK == 0) { v0 += be[c]; v1 += be[c + 1]; }
                        *reinterpret_cast<float2*>(cr + c) = make_float2(v0, v1);
                    }
                }
            }
        }
    }
}

// ---------------------------------------------------------------------------
// Combine (deterministic): out[t] = w0*sum_s Ys[r0] + w1*sum_s Ys[r1]
// ---------------------------------------------------------------------------
__global__ void combine_kernel(float* __restrict__ out)
{
    const int t = blockIdx.x;
    const int j = threadIdx.x;            // 0..191
    const int r0 = g_rowof[2 * t];
    const int r1 = g_rowof[2 * t + 1];
    const float w0 = g_w[2 * t];
    const float w1 = g_w[2 * t + 1];
    float4 sa = make_float4(0.f, 0.f, 0.f, 0.f);
    float4 sb = make_float4(0.f, 0.f, 0.f, 0.f);
    #pragma unroll
    for (int s = 0; s < SPLITK; s++) {
        const float4 a = reinterpret_cast<const float4*>(g_Y[s] + (size_t)r0 * D)[j];
        const float4 b = reinterpret_cast<const float4*>(g_Y[s] + (size_t)r1 * D)[j];
        sa.x += a.x; sa.y += a.y; sa.z += a.z; sa.w += a.w;
        sb.x += b.x; sb.y += b.y; sb.z += b.z; sb.w += b.w;
    }
    float4 o;
    o.x = fmaf(w0, sa.x, w1 * sb.x);
    o.y = fmaf(w0, sa.y, w1 * sb.y);
    o.z = fmaf(w0, sa.z, w1 * sb.z);
    o.w = fmaf(w0, sa.w, w1 * sb.w);
    reinterpret_cast<float4*>(out + (size_t)t * D)[j] = o;
}

// ---------------------------------------------------------------------------
// Launch
// ---------------------------------------------------------------------------
extern "C" void kernel_launch(void* const* d_in, const int* in_sizes, int n_in,
                              void* d_out, int out_size)
{
    const float* x     = (const float*)d_in[0];
    const float* noise = (const float*)d_in[1];
    const float* Wg    = (const float*)d_in[2];
    const float* bg    = (const float*)d_in[3];
    const float* Wn    = (const float*)d_in[4];
    const float* bn    = (const float*)d_in[5];
    const float* W1    = (const float*)d_in[6];
    const float* b1    = (const float*)d_in[7];
    const float* W2    = (const float*)d_in[8];
    const float* b2    = (const float*)d_in[9];
    float* out = (float*)d_out;

    cudaFuncSetAttribute(gemm_f16_kernel<0>,
                         cudaFuncAttributeMaxDynamicSharedMemorySize, SMEM_TOT);
    cudaFuncSetAttribute(gemm_f16_kernel<1>,
                         cudaFuncAttributeMaxDynamicSharedMemorySize, SMEM_TOT);

    reset_kernel<<<1, 32>>>();

    // fused fp32->fp16 conversion (x, W1, W2) + router
    {
        __half* xh;  cudaGetSymbolAddress((void**)&xh,  g_xh);
        __half* w1h; cudaGetSymbolAddress((void**)&w1h, g_W1h);
        __half* w2h; cudaGetSymbolAddress((void**)&w2h, g_W2h);
        const int nx8 = T * D / 8;
        const int nw8 = E * DFF * D / 8;
        const int tot = nx8 + 2 * nw8;
        const int cvtBlocks = (tot + 255) / 256;
        const int routerBlocks = T / 8;          // 8 warps per 256-thread block
        cvt_router_kernel<<<cvtBlocks + routerBlocks, 256>>>(
            x, W1, W2, noise, Wg, bg, Wn, bn, xh, w1h, w2h, nx8, nw8, cvtBlocks);
    }

    // GEMM1: H = relu(xh_gathered @ W1h[e]^T + b1[e])   N=3072, K=768
    {
        __half* w1h; cudaGetSymbolAddress((void**)&w1h, g_W1h);
        dim3 grid(DFF / BN, T / BM, E);
        gemm_f16_kernel<0><<<grid, NTHREADS, SMEM_TOT>>>(w1h, b1);
    }
    // GEMM2: Y = Hh @ W2h[e]^T + b2[e], split-K=4       N=768, K=3072
    {
        __half* w2h; cudaGetSymbolAddress((void**)&w2h, g_W2h);
        dim3 grid(D / BN, T / BM, SPLITK * E);
        gemm_f16_kernel<1><<<grid, NTHREADS, SMEM_TOT>>>(w2h, b2);
    }

    combine_kernel<<<T, D / 4>>>(out);
}

// round 12
// speedup vs baseline: 1.0819x; 1.0819x over previous
#include <cuda_runtime.h>
#include <cuda_fp16.h>
#include <math.h>
#include <stdint.h>

// Problem constants: B=2, S=1024 -> T=2048 tokens; D=768; E=8 experts; DFF=3072; top-2.
#define T    2048
#define D    768
#define E    8
#define DFF  3072

// GEMM tiling (R10 best-measured config): 128x256 CTA tile, 256 threads
// (8 warps, 2x4), 64x64 warp tiles, BK=64 (4 sub-k16 per sync), fp16 mma.sync
// + ldmatrix, 3-stage cp.async, software-pipelined fragment double-buffering.
#define BM 128
#define BN 256
#define BK 64
#define SA 72                       // smem row stride (halves): 64 + 8 pad
#define STAGES 3
#define STG_ROWS (BM + BN)          // 384 rows (A then B) per stage
#define STG_BYTES (STG_ROWS * SA * 2)   // 55296 B per stage
#define SMEM_TOT (STAGES * STG_BYTES)   // 165888 B
#define SPLITK 4

// ---------------------------------------------------------------------------
// Device scratch
// ---------------------------------------------------------------------------
__device__ int    g_cnt[E];
__device__ int    g_tok[E * T];
__device__ int    g_rowof[T * 2];
__device__ float  g_w[T * 2];
__device__ __half g_xh[T * D];                    // x in fp16
__device__ __half g_W1h[(size_t)E * DFF * D];     // W1 in fp16
__device__ __half g_W2h[(size_t)E * D * DFF];     // W2 in fp16
__device__ __half g_Hh[(size_t)E * T * DFF];      // hidden acts, fp16
__device__ float  g_Y[SPLITK][E * T * D];         // split-K partial outputs

__global__ void reset_kernel() {
    if (threadIdx.x < E) g_cnt[threadIdx.x] = 0;
}

// ---------------------------------------------------------------------------
// helpers
// ---------------------------------------------------------------------------
__device__ __forceinline__ uint4 pack8(float4 a, float4 b) {
    __half2 h0 = __floats2half2_rn(a.x, a.y);
    __half2 h1 = __floats2half2_rn(a.z, a.w);
    __half2 h2 = __floats2half2_rn(b.x, b.y);
    __half2 h3 = __floats2half2_rn(b.z, b.w);
    uint4 u;
    u.x = *reinterpret_cast<uint32_t*>(&h0);
    u.y = *reinterpret_cast<uint32_t*>(&h1);
    u.z = *reinterpret_cast<uint32_t*>(&h2);
    u.w = *reinterpret_cast<uint32_t*>(&h3);
    return u;
}
__device__ __forceinline__ uint32_t smem_u32(const void* p) {
    return (uint32_t)__cvta_generic_to_shared(p);
}
__device__ __forceinline__ void cp16(uint32_t dst, const void* src) {
    asm volatile("cp.async.cg.shared.global [%0], [%1], 16;"
                 :: "r"(dst), "l"(src) : "memory");
}
__device__ __forceinline__ void cp_commit() {
    asm volatile("cp.async.commit_group;" ::: "memory");
}
template <int N>
__device__ __forceinline__ void cp_wait() {
    asm volatile("cp.async.wait_group %0;" :: "n"(N) : "memory");
}
__device__ __forceinline__ void ldsm4(uint32_t& r0, uint32_t& r1, uint32_t& r2, uint32_t& r3,
                                      uint32_t addr) {
    asm volatile("ldmatrix.sync.aligned.m8n8.x4.shared.b16 {%0,%1,%2,%3}, [%4];"
                 : "=r"(r0), "=r"(r1), "=r"(r2), "=r"(r3) : "r"(addr));
}
__device__ __forceinline__ void mma_f16(float& c0, float& c1, float& c2, float& c3,
                                        uint32_t a0, uint32_t a1, uint32_t a2, uint32_t a3,
                                        uint32_t b0, uint32_t b1) {
    asm volatile(
        "mma.sync.aligned.m16n8k16.row.col.f32.f16.f16.f32 "
        "{%0,%1,%2,%3}, {%4,%5,%6,%7}, {%8,%9}, {%0,%1,%2,%3};"
        : "+f"(c0), "+f"(c1), "+f"(c2), "+f"(c3)
        : "r"(a0), "r"(a1), "r"(a2), "r"(a3), "r"(b0), "r"(b1));
}

// ---------------------------------------------------------------------------
// Fused fp32->fp16 convert (x, W1, W2) + router (disjoint block ranges, no
// data dependency: router reads fp32 x). Router: one warp per token, noisy
// top-2 gating + atomic per-expert compaction (position-invariant values ->
// deterministic output).
// ---------------------------------------------------------------------------
__device__ void router_body(int warp, int lane,
                            const float* __restrict__ x,
                            const float* __restrict__ noise,
                            const float* __restrict__ Wg,
                            const float* __restrict__ bg,
                            const float* __restrict__ Wn,
                            const float* __restrict__ bn)
{
    const float* xr = x + (size_t)warp * D;
    float xv[D / 32];
    #pragma unroll
    for (int i = 0; i < D / 32; i++) xv[i] = xr[lane + 32 * i];

    float nz[E];
    #pragma unroll
    for (int e = 0; e < E; e++) {
        const float* g  = Wg + e * D;
        const float* nw = Wn + e * D;
        float s1 = 0.f, s2 = 0.f;
        #pragma unroll
        for (int i = 0; i < D / 32; i++) {
            const float xi = xv[i];
            s1 = fmaf(xi, g[lane + 32 * i], s1);
            s2 = fmaf(xi, nw[lane + 32 * i], s2);
        }
        #pragma unroll
        for (int off = 16; off; off >>= 1) {
            s1 += __shfl_xor_sync(0xffffffffu, s1, off);
            s2 += __shfl_xor_sync(0xffffffffu, s2, off);
        }
        const float logit = s1 + bg[e];
        const float nlog  = s2 + bn[e];
        const float sp = fmaxf(nlog, 0.f) + log1pf(expf(-fabsf(nlog)));
        nz[e] = logit + noise[warp * E + e] * sp;
    }

    if (lane == 0) {
        int i0 = 0; float v0 = nz[0];
        #pragma unroll
        for (int e = 1; e < E; e++) if (nz[e] > v0) { v0 = nz[e]; i0 = e; }
        int i1 = -1; float v1 = -3.0e38f;
        #pragma unroll
        for (int e = 0; e < E; e++) if (e != i0 && nz[e] > v1) { v1 = nz[e]; i1 = e; }

        const float ex = expf(v1 - v0);
        const float inv = 1.f / (1.f + ex);

        const int p0 = atomicAdd(&g_cnt[i0], 1);
        const int p1 = atomicAdd(&g_cnt[i1], 1);
        const int r0 = i0 * T + p0;
        const int r1 = i1 * T + p1;
        g_tok[r0] = warp;
        g_tok[r1] = warp;
        g_rowof[2 * warp]     = r0;
        g_rowof[2 * warp + 1] = r1;
        g_w[2 * warp]     = inv;
        g_w[2 * warp + 1] = ex * inv;
    }
}

__global__ void cvt_router_kernel(const float* __restrict__ x,
                                  const float* __restrict__ W1,
                                  const float* __restrict__ W2,
                                  const float* __restrict__ noise,
                                  const float* __restrict__ Wg,
                                  const float* __restrict__ bg,
                                  const float* __restrict__ Wn,
                                  const float* __restrict__ bn,
                                  __half* __restrict__ xh,
                                  __half* __restrict__ w1h,
                                  __half* __restrict__ w2h,
                                  int nx8, int nw8, int cvtBlocks)
{
    if ((int)blockIdx.x < cvtBlocks) {
        const int i = blockIdx.x * blockDim.x + threadIdx.x;
        const float* src; __half* dst; int j;
        if (i < nx8)                 { src = x;  dst = xh;  j = i; }
        else if (i < nx8 + nw8)      { src = W1; dst = w1h; j = i - nx8; }
        else if (i < nx8 + 2 * nw8)  { src = W2; dst = w2h; j = i - nx8 - nw8; }
        else return;
        const float4 a = reinterpret_cast<const float4*>(src)[2 * j];
        const float4 b = reinterpret_cast<const float4*>(src)[2 * j + 1];
        reinterpret_cast<uint4*>(dst)[j] = pack8(a, b);
    } else {
        const int warp = ((blockIdx.x - cvtBlocks) * blockDim.x + threadIdx.x) >> 5;
        const int lane = threadIdx.x & 31;
        if (warp < T) router_body(warp, lane, x, noise, Wg, bg, Wn, bn);
    }
}

// ---------------------------------------------------------------------------
// Fragment ops: warp tile 64x64. A: 4 ldsm.x4, B: 4 ldsm.x4 -> 32 MMAs.
// ---------------------------------------------------------------------------
__device__ __forceinline__ void load_frags(uint32_t (&af)[4][4], uint32_t (&bf)[8][2],
                                           const uint32_t (&aAddr)[4],
                                           const uint32_t (&bAddr)[4], uint32_t off)
{
    #pragma unroll
    for (int mi = 0; mi < 4; mi++)
        ldsm4(af[mi][0], af[mi][1], af[mi][2], af[mi][3], aAddr[mi] + off);
    #pragma unroll
    for (int p = 0; p < 4; p++) {
        uint32_t r0, r1, r2, r3;
        ldsm4(r0, r1, r2, r3, bAddr[p] + off);
        bf[2 * p][0] = r0;     bf[2 * p][1] = r1;
        bf[2 * p + 1][0] = r2; bf[2 * p + 1][1] = r3;
    }
}

__device__ __forceinline__ void mma_tile(float (&acc)[4][8][4],
                                         const uint32_t (&af)[4][4],
                                         const uint32_t (&bf)[8][2])
{
    #pragma unroll
    for (int mi = 0; mi < 4; mi++)
        #pragma unroll
        for (int ni = 0; ni < 8; ni++)
            mma_f16(acc[mi][ni][0], acc[mi][ni][1], acc[mi][ni][2], acc[mi][ni][3],
                    af[mi][0], af[mi][1], af[mi][2], af[mi][3],
                    bf[ni][0], bf[ni][1]);
}

// ---------------------------------------------------------------------------
// Grouped fp16 tensor-core GEMM. 128x256 tile, 64x64 warp tiles, BK=64
// (4 sub-k16 per sync), 3-stage cp.async pipeline, pipelined fragments.
//   MODE 0: H = relu(gather(xh) @ W1h[e]^T + b1);   K=768,  N=3072, out fp16
//   MODE 1: Y = Hh @ W2h[e]^T (+b2 on split 0);     K=768/split x4, N=768, fp32
// ---------------------------------------------------------------------------
template <int MODE>
__global__ __launch_bounds__(256, 1)
void gemm_f16_kernel(const __half* __restrict__ Wh,
                     const float* __restrict__ bias)
{
    constexpr int KROW = (MODE == 0) ? D : DFF;      // row stride of A and W
    constexpr int NTOT = (MODE == 0) ? DFF : D;
    constexpr int KLEN = (MODE == 0) ? D : (DFF / SPLITK);
    constexpr int NKT  = KLEN / BK;

    extern __shared__ __half sm[];

    int e, sK;
    if (MODE == 0) { e = blockIdx.z; sK = 0; }
    else           { e = blockIdx.z & (E - 1); sK = blockIdx.z >> 3; }
    const int ks0 = (MODE == 1) ? sK * KLEN : 0;

    const int cnt = g_cnt[e];
    const int m0  = blockIdx.y * BM;
    if (m0 >= cnt) return;
    const int n0  = blockIdx.x * BN;

    const int tid  = threadIdx.x;
    const int lane = tid & 31;
    const int warp = tid >> 5;
    const int wm   = warp >> 2;        // 0..1  (64-row slices)
    const int wn   = warp & 3;         // 0..3  (64-col slices)
    const int g    = lane >> 2;
    const int q    = lane & 3;

    // ---- staging: 384 rows x 64 halves = 3072 16B-chunks; 12 per thread.
    // chunk c = tid + 256k -> row (tid>>3)+32k, col chunk (tid&7)*8 (k-invariant).
    // k=0..3 -> A region (gathered rows), k=4..11 -> B region (rows r8+32*(k-4)).
    const int r8 = tid >> 3;
    const int c8 = (tid & 7) * 8;
    const uint32_t smb = smem_u32(sm);
    const uint32_t st0 = smb + (uint32_t)(r8 * SA + c8) * 2;   // k stride: 32*SA*2 B

    const __half* srcA[4];
    #pragma unroll
    for (int k = 0; k < 4; k++) {
        const int am = m0 + r8 + 32 * k;
        if (MODE == 0) {
            const int tok = (am < cnt) ? g_tok[e * T + am] : 0;
            srcA[k] = g_xh + (size_t)tok * KROW + c8;
        } else {
            const int r = (am < cnt) ? am : 0;
            srcA[k] = g_Hh + ((size_t)e * T + r) * KROW + ks0 + c8;
        }
    }
    const __half* srcB = Wh + ((size_t)e * NTOT + n0 + r8) * KROW + ks0 + c8;

    // ---- ldmatrix lane base addresses (stage 0, sub-k 0) ----
    uint32_t aAddr[4], bAddr[4];
    {
        const int rin = lane & 15;
        const int ch  = lane >> 4;
        #pragma unroll
        for (int mi = 0; mi < 4; mi++)
            aAddr[mi] = smb + (uint32_t)((wm * 64 + mi * 16 + rin) * SA + ch * 8) * 2;
    }
    {
        const int rin = ((lane >> 4) << 3) + (lane & 7);
        const int ch  = (lane >> 3) & 1;
        #pragma unroll
        for (int p = 0; p < 4; p++)
            bAddr[p] = smb + (uint32_t)((BM + wn * 64 + p * 16 + rin) * SA + ch * 8) * 2;
    }

    float acc[4][8][4];
    #pragma unroll
    for (int mi = 0; mi < 4; mi++)
        #pragma unroll
        for (int ni = 0; ni < 8; ni++)
            #pragma unroll
            for (int r = 0; r < 4; r++) acc[mi][ni][r] = 0.f;

    // stage-fill helper (12 cp16 per thread)
    auto FILL = [&](int stage, int kt) {
        const uint32_t so = (uint32_t)(stage * STG_BYTES);
        const int ko = kt * BK;
        #pragma unroll
        for (int k = 0; k < 4; k++)
            cp16(st0 + so + k * (32 * SA * 2), srcA[k] + ko);
        #pragma unroll
        for (int k = 0; k < 8; k++)
            cp16(st0 + so + (k + 4) * (32 * SA * 2), srcB + (size_t)(32 * k) * KROW + ko);
    };

    // prologue: fill stages 0..1
    #pragma unroll
    for (int s = 0; s < STAGES - 1; s++) { FILL(s, s); cp_commit(); }
    cp_wait<1>();                      // stage 0 complete
    __syncthreads();

    uint32_t af0[4][4], bf0[8][2], af1[4][4], bf1[8][2];
    load_frags(af0, bf0, aAddr, bAddr, 0);   // (kt=0, sub0)

    int cur = 0;
    for (int kt = 0; kt < NKT; kt++) {
        const uint32_t soff = (uint32_t)(cur * STG_BYTES);

        // sub1 frags, then next-stage cp.async, all under MMA(sub0)
        load_frags(af1, bf1, aAddr, bAddr, soff + 32);
        if (kt + STAGES - 1 < NKT) {
            int tgt = cur + 2; if (tgt >= STAGES) tgt -= STAGES;
            FILL(tgt, kt + STAGES - 1);
        }
        cp_commit();
        mma_tile(acc, af0, bf0);                       // sub0

        load_frags(af0, bf0, aAddr, bAddr, soff + 64); // sub2 frags
        mma_tile(acc, af1, bf1);                       // sub1

        load_frags(af1, bf1, aAddr, bAddr, soff + 96); // sub3 frags
        mma_tile(acc, af0, bf0);                       // sub2

        cp_wait<1>();                   // stage kt+1 complete
        __syncthreads();                // barrier drains under sub2's MMAs

        int nxt = cur + 1; if (nxt >= STAGES) nxt = 0;
        if (kt + 1 < NKT)               // (kt+1, sub0) frags under MMA(sub3)
            load_frags(af0, bf0, aAddr, bAddr, (uint32_t)(nxt * STG_BYTES));
        mma_tile(acc, af1, bf1);                       // sub3

        cur = nxt;
    }

    // ---- epilogue ----
    const float* be = bias + (size_t)e * NTOT;
    if (MODE == 0) {
        __half* Cb = g_Hh + (size_t)e * T * NTOT;
        #pragma unroll
        for (int mi = 0; mi < 4; mi++) {
            #pragma unroll
            for (int hh = 0; hh < 2; hh++) {
                const int m = m0 + wm * 64 + mi * 16 + g + hh * 8;
                if (m < cnt) {
                    __half* cr = Cb + (size_t)m * NTOT;
                    #pragma unroll
                    for (int ni = 0; ni < 8; ni++) {
                        const int c = n0 + wn * 64 + ni * 8 + 2 * q;
                        float v0 = acc[mi][ni][2 * hh]     + be[c];
                        float v1 = acc[mi][ni][2 * hh + 1] + be[c + 1];
                        v0 = fmaxf(v0, 0.f); v1 = fmaxf(v1, 0.f);
                        *reinterpret_cast<__half2*>(cr + c) = __floats2half2_rn(v0, v1);
                    }
                }
            }
        }
    } else {
        float* Cb = g_Y[sK] + (size_t)e * T * NTOT;
        #pragma unroll
        for (int mi = 0; mi < 4; mi++) {
            #pragma unroll
            for (int hh = 0; hh < 2; hh++) {
                const int m = m0 + wm * 64 + mi * 16 + g + hh * 8;
                if (m < cnt) {
                    float* cr = Cb + (size_t)m * NTOT;
                    #pragma unroll
                    for (int ni = 0; ni < 8; ni++) {
                        const int c = n0 + wn * 64 + ni * 8 + 2 * q;
                        float v0 = acc[mi][ni][2 * hh];
                        float v1 = acc[mi][ni][2 * hh + 1];
                        if (sK == 0) { v0 += be[c]; v1 += be[c + 1]; }
                        *reinterpret_cast<float2*>(cr + c) = make_float2(v0, v1);
                    }
                }
            }
        }
    }
}

// ---------------------------------------------------------------------------
// Combine (deterministic): out[t] = w0*sum_s Ys[r0] + w1*sum_s Ys[r1]
// ---------------------------------------------------------------------------
__global__ void combine_kernel(float* __restrict__ out)
{
    const int t = blockIdx.x;
    const int j = threadIdx.x;            // 0..191
    const int r0 = g_rowof[2 * t];
    const int r1 = g_rowof[2 * t + 1];
    const float w0 = g_w[2 * t];
    const float w1 = g_w[2 * t + 1];
    float4 sa = make_float4(0.f, 0.f, 0.f, 0.f);
    float4 sb = make_float4(0.f, 0.f, 0.f, 0.f);
    #pragma unroll
    for (int s = 0; s < SPLITK; s++) {
        const float4 a = reinterpret_cast<const float4*>(g_Y[s] + (size_t)r0 * D)[j];
        const float4 b = reinterpret_cast<const float4*>(g_Y[s] + (size_t)r1 * D)[j];
        sa.x += a.x; sa.y += a.y; sa.z += a.z; sa.w += a.w;
        sb.x += b.x; sb.y += b.y; sb.z += b.z; sb.w += b.w;
    }
    float4 o;
    o.x = fmaf(w0, sa.x, w1 * sb.x);
    o.y = fmaf(w0, sa.y, w1 * sb.y);
    o.z = fmaf(w0, sa.z, w1 * sb.z);
    o.w = fmaf(w0, sa.w, w1 * sb.w);
    reinterpret_cast<float4*>(out + (size_t)t * D)[j] = o;
}

// ---------------------------------------------------------------------------
// Launch
// ---------------------------------------------------------------------------
extern "C" void kernel_launch(void* const* d_in, const int* in_sizes, int n_in,
                              void* d_out, int out_size)
{
    const float* x     = (const float*)d_in[0];
    const float* noise = (const float*)d_in[1];
    const float* Wg    = (const float*)d_in[2];
    const float* bg    = (const float*)d_in[3];
    const float* Wn    = (const float*)d_in[4];
    const float* bn    = (const float*)d_in[5];
    const float* W1    = (const float*)d_in[6];
    const float* b1    = (const float*)d_in[7];
    const float* W2    = (const float*)d_in[8];
    const float* b2    = (const float*)d_in[9];
    float* out = (float*)d_out;

    cudaFuncSetAttribute(gemm_f16_kernel<0>,
                         cudaFuncAttributeMaxDynamicSharedMemorySize, SMEM_TOT);
    cudaFuncSetAttribute(gemm_f16_kernel<1>,
                         cudaFuncAttributeMaxDynamicSharedMemorySize, SMEM_TOT);

    reset_kernel<<<1, 32>>>();

    // fused fp32->fp16 conversion (x, W1, W2) + router
    {
        __half* xh;  cudaGetSymbolAddress((void**)&xh,  g_xh);
        __half* w1h; cudaGetSymbolAddress((void**)&w1h, g_W1h);
        __half* w2h; cudaGetSymbolAddress((void**)&w2h, g_W2h);
        const int nx8 = T * D / 8;
        const int nw8 = E * DFF * D / 8;
        const int tot = nx8 + 2 * nw8;
        const int cvtBlocks = (tot + 255) / 256;
        const int routerBlocks = T / 8;          // 8 warps per 256-thread block
        cvt_router_kernel<<<cvtBlocks + routerBlocks, 256>>>(
            x, W1, W2, noise, Wg, bg, Wn, bn, xh, w1h, w2h, nx8, nw8, cvtBlocks);
    }

    // GEMM1: H = relu(xh_gathered @ W1h[e]^T + b1[e])   N=3072, K=768
    {
        __half* w1h; cudaGetSymbolAddress((void**)&w1h, g_W1h);
        dim3 grid(DFF / BN, T / BM, E);
        gemm_f16_kernel<0><<<grid, 256, SMEM_TOT>>>(w1h, b1);
    }
    // GEMM2: Y = Hh @ W2h[e]^T + b2[e], split-K=4       N=768, K=3072
    {
        __half* w2h; cudaGetSymbolAddress((void**)&w2h, g_W2h);
        dim3 grid(D / BN, T / BM, SPLITK * E);
        gemm_f16_kernel<1><<<grid, 256, SMEM_TOT>>>(w2h, b2);
    }

    combine_kernel<<<T, D / 4>>>(out);
}

// round 13
// speedup vs baseline: 1.0938x; 1.0109x over previous
#include <cuda_runtime.h>
#include <cuda_fp16.h>
#include <math.h>
#include <stdint.h>

// Problem constants: B=2, S=1024 -> T=2048 tokens; D=768; E=8 experts; DFF=3072; top-2.
#define T    2048
#define D    768
#define E    8
#define DFF  3072

// GEMM tiling (R10 best-measured config): 128x256 CTA tile, 256 threads
// (8 warps, 2x4), 64x64 warp tiles, BK=64 (4 sub-k16 per sync), fp16 mma.sync
// + ldmatrix, 3-stage cp.async, software-pipelined fragments.
// NEW: persistent CTAs with atomic tile queue (perfect wave packing).
#define BM 128
#define BN 256
#define BK 64
#define SA 72                       // smem row stride (halves): 64 + 8 pad
#define STAGES 3
#define STG_ROWS (BM + BN)          // 384 rows (A then B) per stage
#define STG_BYTES (STG_ROWS * SA * 2)   // 55296 B per stage
#define SMEM_TOT (STAGES * STG_BYTES)   // 165888 B
#define SPLITK 4
#define NSM 148

// ---------------------------------------------------------------------------
// Device scratch
// ---------------------------------------------------------------------------
__device__ int    g_cnt[E];
__device__ int    g_tok[E * T];
__device__ int    g_rowof[T * 2];
__device__ float  g_w[T * 2];
__device__ int    g_q[2];                         // persistent tile queues
__device__ __half g_xh[T * D];                    // x in fp16
__device__ __half g_W1h[(size_t)E * DFF * D];     // W1 in fp16
__device__ __half g_W2h[(size_t)E * D * DFF];     // W2 in fp16
__device__ __half g_Hh[(size_t)E * T * DFF];      // hidden acts, fp16
__device__ float  g_Y[SPLITK][E * T * D];         // split-K partial outputs

__global__ void reset_kernel() {
    if (threadIdx.x < E) g_cnt[threadIdx.x] = 0;
    if (threadIdx.x < 2) g_q[threadIdx.x] = 0;
}

// ---------------------------------------------------------------------------
// fp32 -> fp16 conversion for x, W1, W2 in one launch (8 elems / thread)
// ---------------------------------------------------------------------------
__device__ __forceinline__ uint4 pack8(float4 a, float4 b) {
    __half2 h0 = __floats2half2_rn(a.x, a.y);
    __half2 h1 = __floats2half2_rn(a.z, a.w);
    __half2 h2 = __floats2half2_rn(b.x, b.y);
    __half2 h3 = __floats2half2_rn(b.z, b.w);
    uint4 u;
    u.x = *reinterpret_cast<uint32_t*>(&h0);
    u.y = *reinterpret_cast<uint32_t*>(&h1);
    u.z = *reinterpret_cast<uint32_t*>(&h2);
    u.w = *reinterpret_cast<uint32_t*>(&h3);
    return u;
}

__global__ void cvt3_kernel(const float* __restrict__ x,
                            const float* __restrict__ W1,
                            const float* __restrict__ W2,
                            __half* __restrict__ xh,
                            __half* __restrict__ w1h,
                            __half* __restrict__ w2h,
                            int nx8, int nw8)
{
    const int i = blockIdx.x * blockDim.x + threadIdx.x;
    const float* src; __half* dst; int j;
    if (i < nx8)            { src = x;  dst = xh;  j = i; }
    else if (i < nx8 + nw8) { src = W1; dst = w1h; j = i - nx8; }
    else if (i < nx8 + 2 * nw8) { src = W2; dst = w2h; j = i - nx8 - nw8; }
    else return;
    const float4 a = reinterpret_cast<const float4*>(src)[2 * j];
    const float4 b = reinterpret_cast<const float4*>(src)[2 * j + 1];
    reinterpret_cast<uint4*>(dst)[j] = pack8(a, b);
}

// ---------------------------------------------------------------------------
// Router: one warp per token, noisy top-2 gating + atomic per-expert
// compaction. Row values are position-invariant -> deterministic output.
// ---------------------------------------------------------------------------
__global__ void router_kernel(const float* __restrict__ x,
                              const float* __restrict__ noise,
                              const float* __restrict__ Wg,
                              const float* __restrict__ bg,
                              const float* __restrict__ Wn,
                              const float* __restrict__ bn)
{
    const int warp = (blockIdx.x * blockDim.x + threadIdx.x) >> 5;
    const int lane = threadIdx.x & 31;
    if (warp >= T) return;

    const float* xr = x + (size_t)warp * D;
    float xv[D / 32];
    #pragma unroll
    for (int i = 0; i < D / 32; i++) xv[i] = xr[lane + 32 * i];

    float nz[E];
    #pragma unroll
    for (int e = 0; e < E; e++) {
        const float* g  = Wg + e * D;
        const float* nw = Wn + e * D;
        float s1 = 0.f, s2 = 0.f;
        #pragma unroll
        for (int i = 0; i < D / 32; i++) {
            const float xi = xv[i];
            s1 = fmaf(xi, g[lane + 32 * i], s1);
            s2 = fmaf(xi, nw[lane + 32 * i], s2);
        }
        #pragma unroll
        for (int off = 16; off; off >>= 1) {
            s1 += __shfl_xor_sync(0xffffffffu, s1, off);
            s2 += __shfl_xor_sync(0xffffffffu, s2, off);
        }
        const float logit = s1 + bg[e];
        const float nlog  = s2 + bn[e];
        const float sp = fmaxf(nlog, 0.f) + log1pf(expf(-fabsf(nlog)));
        nz[e] = logit + noise[warp * E + e] * sp;
    }

    if (lane == 0) {
        int i0 = 0; float v0 = nz[0];
        #pragma unroll
        for (int e = 1; e < E; e++) if (nz[e] > v0) { v0 = nz[e]; i0 = e; }
        int i1 = -1; float v1 = -3.0e38f;
        #pragma unroll
        for (int e = 0; e < E; e++) if (e != i0 && nz[e] > v1) { v1 = nz[e]; i1 = e; }

        const float ex = expf(v1 - v0);
        const float inv = 1.f / (1.f + ex);

        const int p0 = atomicAdd(&g_cnt[i0], 1);
        const int p1 = atomicAdd(&g_cnt[i1], 1);
        const int r0 = i0 * T + p0;
        const int r1 = i1 * T + p1;
        g_tok[r0] = warp;
        g_tok[r1] = warp;
        g_rowof[2 * warp]     = r0;
        g_rowof[2 * warp + 1] = r1;
        g_w[2 * warp]     = inv;
        g_w[2 * warp + 1] = ex * inv;
    }
}

// ---------------------------------------------------------------------------
// helpers
// ---------------------------------------------------------------------------
__device__ __forceinline__ uint32_t smem_u32(const void* p) {
    return (uint32_t)__cvta_generic_to_shared(p);
}
__device__ __forceinline__ void cp16(uint32_t dst, const void* src) {
    asm volatile("cp.async.cg.shared.global [%0], [%1], 16;"
                 :: "r"(dst), "l"(src) : "memory");
}
__device__ __forceinline__ void cp_commit() {
    asm volatile("cp.async.commit_group;" ::: "memory");
}
template <int N>
__device__ __forceinline__ void cp_wait() {
    asm volatile("cp.async.wait_group %0;" :: "n"(N) : "memory");
}
__device__ __forceinline__ void ldsm4(uint32_t& r0, uint32_t& r1, uint32_t& r2, uint32_t& r3,
                                      uint32_t addr) {
    asm volatile("ldmatrix.sync.aligned.m8n8.x4.shared.b16 {%0,%1,%2,%3}, [%4];"
                 : "=r"(r0), "=r"(r1), "=r"(r2), "=r"(r3) : "r"(addr));
}
__device__ __forceinline__ void mma_f16(float& c0, float& c1, float& c2, float& c3,
                                        uint32_t a0, uint32_t a1, uint32_t a2, uint32_t a3,
                                        uint32_t b0, uint32_t b1) {
    asm volatile(
        "mma.sync.aligned.m16n8k16.row.col.f32.f16.f16.f32 "
        "{%0,%1,%2,%3}, {%4,%5,%6,%7}, {%8,%9}, {%0,%1,%2,%3};"
        : "+f"(c0), "+f"(c1), "+f"(c2), "+f"(c3)
        : "r"(a0), "r"(a1), "r"(a2), "r"(a3), "r"(b0), "r"(b1));
}

// load one sub-k16 fragment set (A: 4 x ldsm.x4, B: 4 x ldsm.x4)
__device__ __forceinline__ void load_frags(uint32_t (&af)[4][4], uint32_t (&bf)[8][2],
                                           const uint32_t (&aAddr)[4],
                                           const uint32_t (&bAddr)[4], uint32_t off)
{
    #pragma unroll
    for (int mi = 0; mi < 4; mi++)
        ldsm4(af[mi][0], af[mi][1], af[mi][2], af[mi][3], aAddr[mi] + off);
    #pragma unroll
    for (int p = 0; p < 4; p++) {
        uint32_t r0, r1, r2, r3;
        ldsm4(r0, r1, r2, r3, bAddr[p] + off);
        bf[2 * p][0] = r0;     bf[2 * p][1] = r1;
        bf[2 * p + 1][0] = r2; bf[2 * p + 1][1] = r3;
    }
}

// 4x8 grid of m16n8k16 MMAs for one sub-k16
__device__ __forceinline__ void mma_tile(float (&acc)[4][8][4],
                                         const uint32_t (&af)[4][4],
                                         const uint32_t (&bf)[8][2])
{
    #pragma unroll
    for (int mi = 0; mi < 4; mi++)
        #pragma unroll
        for (int ni = 0; ni < 8; ni++)
            mma_f16(acc[mi][ni][0], acc[mi][ni][1], acc[mi][ni][2], acc[mi][ni][3],
                    af[mi][0], af[mi][1], af[mi][2], af[mi][3],
                    bf[ni][0], bf[ni][1]);
}

// ---------------------------------------------------------------------------
// Persistent grouped fp16 tensor-core GEMM. 128x256 tile, 64x64 warp tiles,
// BK=64 (4 sub-k16 per sync), 3-stage cp.async, pipelined fragments.
// 148 CTAs pop tile indices from g_q[MODE] -> perfect wave packing.
// Tile -> output mapping is a pure function of tile id => deterministic.
//   MODE 0: H = relu(gather(xh) @ W1h[e]^T + b1);   K=768,  N=3072, out fp16
//   MODE 1: Y = Hh @ W2h[e]^T (+b2 on split 0);     K=768/split x4, N=768, fp32
// ---------------------------------------------------------------------------
template <int MODE>
__global__ __launch_bounds__(256, 1)
void gemm_f16_kernel(const __half* __restrict__ Wh,
                     const float* __restrict__ bias)
{
    constexpr int KROW = (MODE == 0) ? D : DFF;      // row stride of A and W
    constexpr int NTOT = (MODE == 0) ? DFF : D;
    constexpr int KLEN = (MODE == 0) ? D : (DFF / SPLITK);
    constexpr int NKT  = KLEN / BK;
    constexpr int GX   = NTOT / BN;                  // n-tiles
    constexpr int GY   = T / BM;                     // m-tiles
    constexpr int NT   = GX * GY * ((MODE == 0) ? E : SPLITK * E);

    extern __shared__ __half sm[];
    __shared__ int s_t;

    const int tid  = threadIdx.x;
    const int lane = tid & 31;
    const int warp = tid >> 5;
    const int wm   = warp >> 2;        // 0..1  (64-row slices)
    const int wn   = warp & 3;         // 0..3  (64-col slices)
    const int g    = lane >> 2;
    const int q    = lane & 3;

    // tile-invariant smem addressing
    const int r8 = tid >> 3;
    const int c8 = (tid & 7) * 8;
    const uint32_t smb = smem_u32(sm);
    const uint32_t st0 = smb + (uint32_t)(r8 * SA + c8) * 2;

    uint32_t aAddr[4], bAddr[4];
    {
        const int rin = lane & 15;
        const int ch  = lane >> 4;
        #pragma unroll
        for (int mi = 0; mi < 4; mi++)
            aAddr[mi] = smb + (uint32_t)((wm * 64 + mi * 16 + rin) * SA + ch * 8) * 2;
    }
    {
        const int rin = ((lane >> 4) << 3) + (lane & 7);
        const int ch  = (lane >> 3) & 1;
        #pragma unroll
        for (int p = 0; p < 4; p++)
            bAddr[p] = smb + (uint32_t)((BM + wn * 64 + p * 16 + rin) * SA + ch * 8) * 2;
    }

    for (;;) {
        if (tid == 0) s_t = atomicAdd(&g_q[MODE], 1);
        __syncthreads();
        const int t = s_t;
        __syncthreads();
        if (t >= NT) break;

        // decode tile
        const int xi = t % GX;
        const int yi = (t / GX) % GY;
        const int zi = t / (GX * GY);
        int e, sK;
        if (MODE == 0) { e = zi; sK = 0; }
        else           { e = zi & (E - 1); sK = zi >> 3; }
        const int ks0 = (MODE == 1) ? sK * KLEN : 0;

        const int cnt = g_cnt[e];
        const int m0  = yi * BM;
        if (m0 >= cnt) continue;
        const int n0  = xi * BN;

        // per-tile source pointers
        const __half* srcA[4];
        #pragma unroll
        for (int k = 0; k < 4; k++) {
            const int am = m0 + r8 + 32 * k;
            if (MODE == 0) {
                const int tok = (am < cnt) ? g_tok[e * T + am] : 0;
                srcA[k] = g_xh + (size_t)tok * KROW + c8;
            } else {
                const int r = (am < cnt) ? am : 0;
                srcA[k] = g_Hh + ((size_t)e * T + r) * KROW + ks0 + c8;
            }
        }
        const __half* srcB = Wh + ((size_t)e * NTOT + n0 + r8) * KROW + ks0 + c8;

        float acc[4][8][4];
        #pragma unroll
        for (int mi = 0; mi < 4; mi++)
            #pragma unroll
            for (int ni = 0; ni < 8; ni++)
                #pragma unroll
                for (int r = 0; r < 4; r++) acc[mi][ni][r] = 0.f;

        auto FILL = [&](int stage, int kt) {
            const uint32_t so = (uint32_t)(stage * STG_BYTES);
            const int ko = kt * BK;
            #pragma unroll
            for (int k = 0; k < 4; k++)
                cp16(st0 + so + k * (32 * SA * 2), srcA[k] + ko);
            #pragma unroll
            for (int k = 0; k < 8; k++)
                cp16(st0 + so + (k + 4) * (32 * SA * 2), srcB + (size_t)(32 * k) * KROW + ko);
        };

        // prologue: fill stages 0..1
        #pragma unroll
        for (int s = 0; s < STAGES - 1; s++) { FILL(s, s); cp_commit(); }
        cp_wait<1>();
        __syncthreads();

        uint32_t af0[4][4], bf0[8][2], af1[4][4], bf1[8][2];
        load_frags(af0, bf0, aAddr, bAddr, 0);

        int cur = 0;
        for (int kt = 0; kt < NKT; kt++) {
            const uint32_t soff = (uint32_t)(cur * STG_BYTES);

            load_frags(af1, bf1, aAddr, bAddr, soff + 32);
            if (kt + STAGES - 1 < NKT) {
                int tgt = cur + 2; if (tgt >= STAGES) tgt -= STAGES;
                FILL(tgt, kt + STAGES - 1);
            }
            cp_commit();
            mma_tile(acc, af0, bf0);                       // sub0

            load_frags(af0, bf0, aAddr, bAddr, soff + 64); // sub2 frags
            mma_tile(acc, af1, bf1);                       // sub1

            load_frags(af1, bf1, aAddr, bAddr, soff + 96); // sub3 frags
            mma_tile(acc, af0, bf0);                       // sub2

            cp_wait<1>();
            __syncthreads();

            int nxt = cur + 1; if (nxt >= STAGES) nxt = 0;
            if (kt + 1 < NKT)
                load_frags(af0, bf0, aAddr, bAddr, (uint32_t)(nxt * STG_BYTES));
            mma_tile(acc, af1, bf1);                       // sub3

            cur = nxt;
        }

        // ---- epilogue ----
        const float* be = bias + (size_t)e * NTOT;
        if (MODE == 0) {
            __half* Cb = g_Hh + (size_t)e * T * NTOT;
            #pragma unroll
            for (int mi = 0; mi < 4; mi++) {
                #pragma unroll
                for (int hh = 0; hh < 2; hh++) {
                    const int m = m0 + wm * 64 + mi * 16 + g + hh * 8;
                    if (m < cnt) {
                        __half* cr = Cb + (size_t)m * NTOT;
                        #pragma unroll
                        for (int ni = 0; ni < 8; ni++) {
                            const int c = n0 + wn * 64 + ni * 8 + 2 * q;
                            float v0 = acc[mi][ni][2 * hh]     + be[c];
                            float v1 = acc[mi][ni][2 * hh + 1] + be[c + 1];
                            v0 = fmaxf(v0, 0.f); v1 = fmaxf(v1, 0.f);
                            *reinterpret_cast<__half2*>(cr + c) = __floats2half2_rn(v0, v1);
                        }
                    }
                }
            }
        } else {
            float* Cb = g_Y[sK] + (size_t)e * T * NTOT;
            #pragma unroll
            for (int mi = 0; mi < 4; mi++) {
                #pragma unroll
                for (int hh = 0; hh < 2; hh++) {
                    const int m = m0 + wm * 64 + mi * 16 + g + hh * 8;
                    if (m < cnt) {
                        float* cr = Cb + (size_t)m * NTOT;
                        #pragma unroll
                        for (int ni = 0; ni < 8; ni++) {
                            const int c = n0 + wn * 64 + ni * 8 + 2 * q;
                            float v0 = acc[mi][ni][2 * hh];
                            float v1 = acc[mi][ni][2 * hh + 1];
                            if (sK == 0) { v0 += be[c]; v1 += be[c + 1]; }
                            *reinterpret_cast<float2*>(cr + c) = make_float2(v0, v1);
                        }
                    }
                }
            }
        }
    }
}

// ---------------------------------------------------------------------------
// Combine (deterministic): out[t] = w0*sum_s Ys[r0] + w1*sum_s Ys[r1]
// ---------------------------------------------------------------------------
__global__ void combine_kernel(float* __restrict__ out)
{
    const int t = blockIdx.x;
    const int j = threadIdx.x;            // 0..191
    const int r0 = g_rowof[2 * t];
    const int r1 = g_rowof[2 * t + 1];
    const float w0 = g_w[2 * t];
    const float w1 = g_w[2 * t + 1];
    float4 sa = make_float4(0.f, 0.f, 0.f, 0.f);
    float4 sb = make_float4(0.f, 0.f, 0.f, 0.f);
    #pragma unroll
    for (int s = 0; s < SPLITK; s++) {
        const float4 a = reinterpret_cast<const float4*>(g_Y[s] + (size_t)r0 * D)[j];
        const float4 b = reinterpret_cast<const float4*>(g_Y[s] + (size_t)r1 * D)[j];
        sa.x += a.x; sa.y += a.y; sa.z += a.z; sa.w += a.w;
        sb.x += b.x; sb.y += b.y; sb.z += b.z; sb.w += b.w;
    }
    float4 o;
    o.x = fmaf(w0, sa.x, w1 * sb.x);
    o.y = fmaf(w0, sa.y, w1 * sb.y);
    o.z = fmaf(w0, sa.z, w1 * sb.z);
    o.w = fmaf(w0, sa.w, w1 * sb.w);
    reinterpret_cast<float4*>(out + (size_t)t * D)[j] = o;
}

// ---------------------------------------------------------------------------
// Launch
// ---------------------------------------------------------------------------
extern "C" void kernel_launch(void* const* d_in, const int* in_sizes, int n_in,
                              void* d_out, int out_size)
{
    const float* x     = (const float*)d_in[0];
    const float* noise = (const float*)d_in[1];
    const float* Wg    = (const float*)d_in[2];
    const float* bg    = (const float*)d_in[3];
    const float* Wn    = (const float*)d_in[4];
    const float* bn    = (const float*)d_in[5];
    const float* W1    = (const float*)d_in[6];
    const float* b1    = (const float*)d_in[7];
    const float* W2    = (const float*)d_in[8];
    const float* b2    = (const float*)d_in[9];
    float* out = (float*)d_out;

    cudaFuncSetAttribute(gemm_f16_kernel<0>,
                         cudaFuncAttributeMaxDynamicSharedMemorySize, SMEM_TOT);
    cudaFuncSetAttribute(gemm_f16_kernel<1>,
                         cudaFuncAttributeMaxDynamicSharedMemorySize, SMEM_TOT);

    reset_kernel<<<1, 32>>>();

    // fp32 -> fp16 conversions (x, W1, W2) in one launch
    {
        __half* xh;  cudaGetSymbolAddress((void**)&xh,  g_xh);
        __half* w1h; cudaGetSymbolAddress((void**)&w1h, g_W1h);
        __half* w2h; cudaGetSymbolAddress((void**)&w2h, g_W2h);
        const int nx8 = T * D / 8;
        const int nw8 = E * DFF * D / 8;
        const int tot = nx8 + 2 * nw8;
        cvt3_kernel<<<(tot + 255) / 256, 256>>>(x, W1, W2, xh, w1h, w2h, nx8, nw8);
    }

    router_kernel<<<T / 8, 256>>>(x, noise, Wg, bg, Wn, bn);

    // GEMM1 (persistent): H = relu(xh_gathered @ W1h[e]^T + b1[e])
    {
        __half* w1h; cudaGetSymbolAddress((void**)&w1h, g_W1h);
        gemm_f16_kernel<0><<<NSM, 256, SMEM_TOT>>>(w1h, b1);
    }
    // GEMM2 (persistent): Y = Hh @ W2h[e]^T + b2[e], split-K=4
    {
        __half* w2h; cudaGetSymbolAddress((void**)&w2h, g_W2h);
        gemm_f16_kernel<1><<<NSM, 256, SMEM_TOT>>>(w2h, b2);
    }

    combine_kernel<<<T, D / 4>>>(out);
}